// round 9
// baseline (speedup 1.0000x reference)
#include <cuda_runtime.h>
#include <cuda_fp16.h>
#include <cstdint>

// ----------------------------------------------------------------------------
// GCNConv: out = (D^-1/2 A D^-1/2)(X W) + bias,  N=8192, DIN=DOUT=256, fp32
//   K1: deg = rowsum(adj)+l ; d = deg^-1/2 ; ALSO writes g_Ah = fp16(adj)
//   K2: g_ZTh[n,k] = fp16_rne( d[k] * (X@W)[k,n] )   (K-major B operand)
//   K3: out[m,n] = d[m] * sum_k Ah[m,k]*ZTh[n,k] + bias[n]
//       mma.sync.m16n8k16.f32.f16.f16.f32 (2x MACs/instr vs tf32 at the
//       same 10-bit mantissa), BK=32, 4-stage cp.async ring.
// ----------------------------------------------------------------------------

#define N_NODES 8192
#define FDIM    256

__device__ float  g_d[N_NODES];
__device__ __half g_Ah[(size_t)N_NODES * N_NODES];   // fp16 adjacency mirror
__device__ __half g_ZTh[FDIM * (size_t)N_NODES];     // fp16 d*(XW)^T, K-major

// ---------------- helpers ---------------------------------------------------
__device__ __forceinline__ uint32_t smem_u32(const void* p) {
    uint32_t a;
    asm("{ .reg .u64 t; cvta.to.shared.u64 t, %1; cvt.u32.u64 %0, t; }"
        : "=r"(a) : "l"(p));
    return a;
}
__device__ __forceinline__ void cp16(uint32_t dst, const void* src) {
    asm volatile("cp.async.cg.shared.global [%0], [%1], 16;"
                 :: "r"(dst), "l"(src) : "memory");
}
__device__ __forceinline__ void mma_16n8k16(float* d, const uint32_t* a,
                                            const uint32_t* b) {
    asm volatile(
        "mma.sync.aligned.m16n8k16.row.col.f32.f16.f16.f32 "
        "{%0,%1,%2,%3}, {%4,%5,%6,%7}, {%8,%9}, {%0,%1,%2,%3};"
        : "+f"(d[0]), "+f"(d[1]), "+f"(d[2]), "+f"(d[3])
        : "r"(a[0]), "r"(a[1]), "r"(a[2]), "r"(a[3]), "r"(b[0]), "r"(b[1]));
}

// robust scalar 'l' reader: handles int32/int64 (small) and fp32 encodings
__device__ __forceinline__ float read_l(const void* p) {
    int i = *(const int*)p;
    if (i >= 0 && i < (1 << 24)) return (float)i;
    return __int_as_float(i);
}

// ---------------- K1: degree + D^{-1/2} + fp16 mirror of adj ----------------
__global__ __launch_bounds__(256) void k_deg(const float* __restrict__ adj,
                                             const void* __restrict__ lptr) {
    int row = blockIdx.x;
    const float4* p = (const float4*)(adj + (size_t)row * N_NODES);
    __half* ah = g_Ah + (size_t)row * N_NODES;
    float s = 0.f;
#pragma unroll
    for (int i = 0; i < 8; i++) {
        int idx = threadIdx.x + i * 256;
        float4 v = p[idx];
        s += (v.x + v.y) + (v.z + v.w);
        __half2 h01 = __floats2half2_rn(v.x, v.y);
        __half2 h23 = __floats2half2_rn(v.z, v.w);
        uint2 pk;
        pk.x = *(uint32_t*)&h01;
        pk.y = *(uint32_t*)&h23;
        *(uint2*)(ah + 4 * idx) = pk;
    }
#pragma unroll
    for (int o = 16; o; o >>= 1) s += __shfl_xor_sync(0xffffffffu, s, o);
    __shared__ float ws[8];
    if ((threadIdx.x & 31) == 0) ws[threadIdx.x >> 5] = s;
    __syncthreads();
    if (threadIdx.x == 0) {
        float t = 0.f;
#pragma unroll
        for (int w = 0; w < 8; w++) t += ws[w];
        float deg = t + read_l(lptr);
        g_d[row] = deg > 0.f ? rsqrtf(deg) : 0.f;
    }
}

// ---------------- K2: ZTh = fp16( d ∘ (X@W) ), transposed -------------------
__global__ __launch_bounds__(256) void k_support(const float* __restrict__ X,
                                                 const float* __restrict__ W) {
    __shared__ float Xs[64][17];
    __shared__ float Ws[16][65];
    int k0 = blockIdx.x * 64, n0 = blockIdx.y * 64;
    int t = threadIdx.x;
    int tx = t & 15, ty = t >> 4;
    float acc[4][4] = {};
    for (int c0 = 0; c0 < FDIM; c0 += 16) {
#pragma unroll
        for (int e = t; e < 1024; e += 256) {
            int r = e >> 4, c = e & 15;
            Xs[r][c] = X[(size_t)(k0 + r) * FDIM + c0 + c];
        }
#pragma unroll
        for (int e = t; e < 1024; e += 256) {
            int c = e >> 6, n = e & 63;
            Ws[c][n] = W[(size_t)(c0 + c) * FDIM + n0 + n];
        }
        __syncthreads();
#pragma unroll
        for (int c = 0; c < 16; c++) {
            float a0 = Xs[ty * 4 + 0][c], a1 = Xs[ty * 4 + 1][c];
            float a2 = Xs[ty * 4 + 2][c], a3 = Xs[ty * 4 + 3][c];
#pragma unroll
            for (int j = 0; j < 4; j++) {
                float b = Ws[c][tx * 4 + j];
                acc[0][j] += a0 * b; acc[1][j] += a1 * b;
                acc[2][j] += a2 * b; acc[3][j] += a3 * b;
            }
        }
        __syncthreads();
    }
#pragma unroll
    for (int r = 0; r < 4; r++) {
        int k = k0 + ty * 4 + r;
        float dk = g_d[k];
#pragma unroll
        for (int j = 0; j < 4; j++) {
            int n = n0 + tx * 4 + j;
            g_ZTh[(size_t)n * N_NODES + k] = __float2half_rn(dk * acc[r][j]);
        }
    }
}

// ---------------- K3: mma.sync fp16 m16n8k16 GEMM ---------------------------
// BM=64, BN=256, BK=32 (2 k16-steps/iter), 4-stage cp.async ring, 128 CTAs.
// 8 warps in 2x4 grid; warp tile 32x64 (2 mt x 8 nt m16n8k16 tiles).
// Smem fp16, row stride 56 halves (112 B: 16B-aligned rows; fragment LDS
// bank = (28g + t) mod 32 -> all 32 distinct -> conflict-free).
#define BM     64
#define BN     256
#define BK     32
#define NIT    (N_NODES / BK)     // 256
#define STAGES 4
#define STRH   56
#define A_STH  (BM * STRH)        // 3584 halves
#define B_STH  (BN * STRH)        // 14336 halves
#define SMEM_BYTES (STAGES * (A_STH + B_STH) * 2 + FDIM * 4)   // 144384

__device__ __forceinline__ void issue_stage(int m0, __half* sA, __half* sB,
                                            int tid, int it, int s) {
    int k0 = it * BK;
    {                               // A: 64 rows x 32 halves (256 x 16B)
        int r = tid >> 2, c8 = (tid & 3) * 8;
        cp16(smem_u32(sA + s * A_STH + r * STRH + c8),
             g_Ah + (size_t)(m0 + r) * N_NODES + k0 + c8);
    }
#pragma unroll
    for (int j = 0; j < 4; j++) {   // B: 256 rows x 32 halves (1024 x 16B)
        int f = tid + j * 256, r = f >> 2, c8 = (f & 3) * 8;
        cp16(smem_u32(sB + s * B_STH + r * STRH + c8),
             g_ZTh + (size_t)r * N_NODES + k0 + c8);
    }
}

__global__ __launch_bounds__(256, 1)
void k_gemm(const float* __restrict__ bias, float* __restrict__ out) {
    extern __shared__ __half smh[];
    __half* sA = smh;
    __half* sB = smh + STAGES * A_STH;
    float* sBias = (float*)(smh + STAGES * (A_STH + B_STH));

    int tid = threadIdx.x, wid = tid >> 5, lane = tid & 31;
    int grp = lane >> 2, tig = lane & 3;
    int warpm = wid >> 2, warpn = wid & 3;   // 2 x 4 warp grid
    int m0 = blockIdx.x * BM;

    if (tid < FDIM) sBias[tid] = bias[tid];

    issue_stage(m0, sA, sB, tid, 0, 0);
    asm volatile("cp.async.commit_group;" ::: "memory");
    issue_stage(m0, sA, sB, tid, 1, 1);
    asm volatile("cp.async.commit_group;" ::: "memory");
    issue_stage(m0, sA, sB, tid, 2, 2);
    asm volatile("cp.async.commit_group;" ::: "memory");

    float acc[2][8][4] = {};
    int s_cur = 0, s_nxt = STAGES - 1;

    int ar0 = warpm * 32 + grp;    // A rows: ar0(+8) (+16 for mt=1)
    int bn0 = warpn * 64 + grp;    // B rows: bn0 + nt*8

#pragma unroll 1
    for (int it = 0; it < NIT; ++it) {
        asm volatile("cp.async.wait_group %0;" :: "n"(STAGES - 2) : "memory");
        __syncthreads();
        const __half* As = sA + s_cur * A_STH;
        const __half* Bs = sB + s_cur * B_STH;
#pragma unroll
        for (int kk = 0; kk < 2; kk++) {
            int kb = kk * 16 + 2 * tig;
            uint32_t a[2][4];
#pragma unroll
            for (int mt = 0; mt < 2; mt++) {
                int r0 = ar0 + mt * 16;
                a[mt][0] = *(const uint32_t*)(As + r0 * STRH + kb);
                a[mt][1] = *(const uint32_t*)(As + (r0 + 8) * STRH + kb);
                a[mt][2] = *(const uint32_t*)(As + r0 * STRH + kb + 8);
                a[mt][3] = *(const uint32_t*)(As + (r0 + 8) * STRH + kb + 8);
            }
            uint32_t b[8][2];
#pragma unroll
            for (int nt = 0; nt < 8; nt++) {
                int n = bn0 + nt * 8;
                b[nt][0] = *(const uint32_t*)(Bs + n * STRH + kb);
                b[nt][1] = *(const uint32_t*)(Bs + n * STRH + kb + 8);
            }
#pragma unroll
            for (int mt = 0; mt < 2; mt++)
#pragma unroll
                for (int nt = 0; nt < 8; nt++)
                    mma_16n8k16(acc[mt][nt], a[mt], b[nt]);
        }
        if (it + STAGES - 1 < NIT)
            issue_stage(m0, sA, sB, tid, it + STAGES - 1, s_nxt);
        asm volatile("cp.async.commit_group;" ::: "memory");
        if (++s_cur == STAGES) s_cur = 0;
        if (++s_nxt == STAGES) s_nxt = 0;
    }

    // ---- epilogue: out = d[m]*acc + bias ----
#pragma unroll
    for (int mt = 0; mt < 2; mt++) {
        int r0 = m0 + warpm * 32 + mt * 16 + grp;
        float d0 = g_d[r0], d1 = g_d[r0 + 8];
        float* o0 = out + (size_t)r0 * FDIM;
        float* o1 = out + (size_t)(r0 + 8) * FDIM;
#pragma unroll
        for (int nt = 0; nt < 8; nt++) {
            int n = warpn * 64 + nt * 8 + 2 * tig;
            float2 v0, v1;
            v0.x = acc[mt][nt][0] * d0 + sBias[n];
            v0.y = acc[mt][nt][1] * d0 + sBias[n + 1];
            v1.x = acc[mt][nt][2] * d1 + sBias[n];
            v1.y = acc[mt][nt][3] * d1 + sBias[n + 1];
            *(float2*)(o0 + n) = v0;
            *(float2*)(o1 + n) = v1;
        }
    }
}

// ---------------- launch ----------------------------------------------------
extern "C" void kernel_launch(void* const* d_in, const int* in_sizes, int n_in,
                              void* d_out, int out_size) {
    const float* adj  = (const float*)d_in[0];
    const float* X    = (const float*)d_in[1];
    const float* W    = (const float*)d_in[2];
    const float* bias = (const float*)d_in[3];
    const void*  lptr = d_in[4];
    float* out = (float*)d_out;

    cudaFuncSetAttribute(k_gemm, cudaFuncAttributeMaxDynamicSharedMemorySize,
                         SMEM_BYTES);

    k_deg<<<N_NODES, 256>>>(adj, lptr);
    k_support<<<dim3(N_NODES / 64, FDIM / 64), 256>>>(X, W);
    k_gemm<<<N_NODES / BM, 256, SMEM_BYTES>>>(bias, out);
}

// round 10
// speedup vs baseline: 1.0881x; 1.0881x over previous
#include <cuda_runtime.h>
#include <cstdint>

// ----------------------------------------------------------------------------
// GCNConv: out = (D^-1/2 A D^-1/2)(X W) + bias,  N=8192, DIN=DOUT=256, fp32
//   K1: deg = rowsum(adj)+l ; d = deg^-1/2
//   K2: ZT[n,k] = tf32_rne( d[k] * (X@W)[k,n] )     (K-major B operand)
//   K3: split-K=2 tf32 mma.sync GEMM, 2 CTAs/SM co-resident (independent
//       barriers fill each other's latency stalls), partials to scratch.
//   K4: out = d[m]*(p0+p1) + bias
// ----------------------------------------------------------------------------

#define N_NODES 8192
#define FDIM    256

__device__ float g_d[N_NODES];
__device__ float g_ZT[FDIM * (size_t)N_NODES];
__device__ float g_part[2 * (size_t)N_NODES * FDIM];   // split-K partials

// ---------------- helpers ---------------------------------------------------
__device__ __forceinline__ uint32_t smem_u32(const void* p) {
    uint32_t a;
    asm("{ .reg .u64 t; cvta.to.shared.u64 t, %1; cvt.u32.u64 %0, t; }"
        : "=r"(a) : "l"(p));
    return a;
}
__device__ __forceinline__ void cp16(uint32_t dst, const void* src) {
    asm volatile("cp.async.cg.shared.global [%0], [%1], 16;"
                 :: "r"(dst), "l"(src) : "memory");
}
__device__ __forceinline__ uint32_t f2tf32(float x) {
    uint32_t r;
    asm("cvt.rna.tf32.f32 %0, %1;" : "=r"(r) : "f"(x));
    return r;
}
__device__ __forceinline__ void mma_16n8k8(float* d, const uint32_t* a,
                                           const uint32_t* b) {
    asm volatile(
        "mma.sync.aligned.m16n8k8.row.col.f32.tf32.tf32.f32 "
        "{%0,%1,%2,%3}, {%4,%5,%6,%7}, {%8,%9}, {%0,%1,%2,%3};"
        : "+f"(d[0]), "+f"(d[1]), "+f"(d[2]), "+f"(d[3])
        : "r"(a[0]), "r"(a[1]), "r"(a[2]), "r"(a[3]), "r"(b[0]), "r"(b[1]));
}

// robust scalar 'l' reader: handles int32/int64 (small) and fp32 encodings
__device__ __forceinline__ float read_l(const void* p) {
    int i = *(const int*)p;
    if (i >= 0 && i < (1 << 24)) return (float)i;
    return __int_as_float(i);
}

// ---------------- K1: degree + D^{-1/2} -------------------------------------
__global__ __launch_bounds__(256) void k_deg(const float* __restrict__ adj,
                                             const void* __restrict__ lptr) {
    int row = blockIdx.x;
    const float4* p = (const float4*)(adj + (size_t)row * N_NODES);
    float s = 0.f;
#pragma unroll
    for (int i = 0; i < 8; i++) {
        float4 v = p[threadIdx.x + i * 256];
        s += (v.x + v.y) + (v.z + v.w);
    }
#pragma unroll
    for (int o = 16; o; o >>= 1) s += __shfl_xor_sync(0xffffffffu, s, o);
    __shared__ float ws[8];
    if ((threadIdx.x & 31) == 0) ws[threadIdx.x >> 5] = s;
    __syncthreads();
    if (threadIdx.x == 0) {
        float t = 0.f;
#pragma unroll
        for (int w = 0; w < 8; w++) t += ws[w];
        float deg = t + read_l(lptr);
        g_d[row] = deg > 0.f ? rsqrtf(deg) : 0.f;
    }
}

// ---------------- K2: ZT = d ∘ (X@W), transposed + tf32-rne -----------------
__global__ __launch_bounds__(256) void k_support(const float* __restrict__ X,
                                                 const float* __restrict__ W) {
    __shared__ float Xs[64][17];
    __shared__ float Ws[16][65];
    int k0 = blockIdx.x * 64, n0 = blockIdx.y * 64;
    int t = threadIdx.x;
    int tx = t & 15, ty = t >> 4;
    float acc[4][4] = {};
    for (int c0 = 0; c0 < FDIM; c0 += 16) {
#pragma unroll
        for (int e = t; e < 1024; e += 256) {
            int r = e >> 4, c = e & 15;
            Xs[r][c] = X[(size_t)(k0 + r) * FDIM + c0 + c];
        }
#pragma unroll
        for (int e = t; e < 1024; e += 256) {
            int c = e >> 6, n = e & 63;
            Ws[c][n] = W[(size_t)(c0 + c) * FDIM + n0 + n];
        }
        __syncthreads();
#pragma unroll
        for (int c = 0; c < 16; c++) {
            float a0 = Xs[ty * 4 + 0][c], a1 = Xs[ty * 4 + 1][c];
            float a2 = Xs[ty * 4 + 2][c], a3 = Xs[ty * 4 + 3][c];
#pragma unroll
            for (int j = 0; j < 4; j++) {
                float b = Ws[c][tx * 4 + j];
                acc[0][j] += a0 * b; acc[1][j] += a1 * b;
                acc[2][j] += a2 * b; acc[3][j] += a3 * b;
            }
        }
        __syncthreads();
    }
#pragma unroll
    for (int r = 0; r < 4; r++) {
        int k = k0 + ty * 4 + r;
        float dk = g_d[k];
#pragma unroll
        for (int j = 0; j < 4; j++) {
            int n = n0 + tx * 4 + j;
            g_ZT[(size_t)n * N_NODES + k] =
                __uint_as_float(f2tf32(dk * acc[r][j]));
        }
    }
}

// ---------------- K3: split-K tf32 GEMM, 2 CTAs/SM --------------------------
// Grid 256 = 128 m-tiles x 2 k-splits; each CTA: BM=64, BN=256, K half=4096,
// BK=32 (NIT=128), 2-stage cp.async double buffer, 8 warps (2x4, 32x64 tile).
// Row stride 36 floats: fragment LDS bank = (4*grp+tig)%32 -> conflict-free.
#define BM     64
#define BN     256
#define BK     32
#define KSPL   2
#define KHALF  (N_NODES / KSPL)   // 4096
#define NIT    (KHALF / BK)       // 128
#define STAGES 2
#define ASTR   36
#define A_ST   (BM * ASTR)        // 2304 floats
#define B_ST   (BN * ASTR)        // 9216 floats
#define SMEM_BYTES (STAGES * (A_ST + B_ST) * 4)   // 92160

__device__ __forceinline__ void issue_stage(const float* __restrict__ adj,
                                            int m0, int kbase, float* sA,
                                            float* sB, int tid, int it, int s) {
    int k0 = kbase + it * BK;
#pragma unroll
    for (int j = 0; j < 2; j++) {   // A: 64 rows x 32 floats
        int f = tid + j * 256, r = f >> 3, c4 = (f & 7) * 4;
        cp16(smem_u32(sA + s * A_ST + r * ASTR + c4),
             adj + (size_t)(m0 + r) * N_NODES + k0 + c4);
    }
#pragma unroll
    for (int j = 0; j < 8; j++) {   // B: 256 rows x 32 floats
        int f = tid + j * 256, r = f >> 3, c4 = (f & 7) * 4;
        cp16(smem_u32(sB + s * B_ST + r * ASTR + c4),
             g_ZT + (size_t)r * N_NODES + k0 + c4);
    }
}

__global__ __launch_bounds__(256, 2)
void k_gemm(const float* __restrict__ adj) {
    extern __shared__ float sm[];
    float* sA = sm;
    float* sB = sm + STAGES * A_ST;

    int tid = threadIdx.x, wid = tid >> 5, lane = tid & 31;
    int grp = lane >> 2, tig = lane & 3;
    int warpm = wid >> 2, warpn = wid & 3;   // 2 x 4 warp grid
    int m0 = (blockIdx.x >> 1) * BM;
    int split = blockIdx.x & 1;
    int kbase = split * KHALF;

    issue_stage(adj, m0, kbase, sA, sB, tid, 0, 0);
    asm volatile("cp.async.commit_group;" ::: "memory");

    float acc[2][8][4] = {};
    int ar0 = warpm * 32 + grp;
    int bn0 = warpn * 64 + grp;

#pragma unroll 1
    for (int it = 0; it < NIT; ++it) {
        // issue next stage first, then wait for current (allow 1 pending)
        if (it + 1 < NIT)
            issue_stage(adj, m0, kbase, sA, sB, tid, it + 1, (it + 1) & 1);
        asm volatile("cp.async.commit_group;" ::: "memory");
        asm volatile("cp.async.wait_group 1;" ::: "memory");
        __syncthreads();

        const float* As = sA + (it & 1) * A_ST;
        const float* Bs = sB + (it & 1) * B_ST;
#pragma unroll
        for (int kk = 0; kk < 4; kk++) {
            int kb = kk * 8 + tig;
            uint32_t a[2][4];
#pragma unroll
            for (int mt = 0; mt < 2; mt++) {
                int r0 = ar0 + mt * 16;
                a[mt][0] = f2tf32(As[r0 * ASTR + kb]);
                a[mt][1] = f2tf32(As[(r0 + 8) * ASTR + kb]);
                a[mt][2] = f2tf32(As[r0 * ASTR + kb + 4]);
                a[mt][3] = f2tf32(As[(r0 + 8) * ASTR + kb + 4]);
            }
            uint32_t b[8][2];
#pragma unroll
            for (int nt = 0; nt < 8; nt++) {
                int n = bn0 + nt * 8;
                b[nt][0] = __float_as_uint(Bs[n * ASTR + kb]);
                b[nt][1] = __float_as_uint(Bs[n * ASTR + kb + 4]);
            }
#pragma unroll
            for (int mt = 0; mt < 2; mt++)
#pragma unroll
                for (int nt = 0; nt < 8; nt++)
                    mma_16n8k8(acc[mt][nt], a[mt], b[nt]);
        }
        __syncthreads();   // protect stage reuse (2-deep ring)
    }

    // ---- write raw partials ----
    float* part = g_part + (size_t)split * N_NODES * FDIM;
#pragma unroll
    for (int mt = 0; mt < 2; mt++) {
        int r0 = m0 + warpm * 32 + mt * 16 + grp;
        float* p0 = part + (size_t)r0 * FDIM;
        float* p1 = part + (size_t)(r0 + 8) * FDIM;
#pragma unroll
        for (int nt = 0; nt < 8; nt++) {
            int n = warpn * 64 + nt * 8 + 2 * tig;
            *(float2*)(p0 + n) = make_float2(acc[mt][nt][0], acc[mt][nt][1]);
            *(float2*)(p1 + n) = make_float2(acc[mt][nt][2], acc[mt][nt][3]);
        }
    }
}

// ---------------- K4: out = d[m]*(p0+p1) + bias -----------------------------
__global__ __launch_bounds__(256) void k_out(const float* __restrict__ bias,
                                             float* __restrict__ out) {
    int idx = blockIdx.x * 256 + threadIdx.x;       // one float4 per thread
    int m = idx >> 6, c4 = (idx & 63) * 4;
    float dv = g_d[m];
    const float4 p0 = *(const float4*)(g_part + (size_t)m * FDIM + c4);
    const float4 p1 = *(const float4*)(g_part + (size_t)(N_NODES + m) * FDIM + c4);
    const float4 bv = *(const float4*)(bias + c4);
    float4 o;
    o.x = (p0.x + p1.x) * dv + bv.x;
    o.y = (p0.y + p1.y) * dv + bv.y;
    o.z = (p0.z + p1.z) * dv + bv.z;
    o.w = (p0.w + p1.w) * dv + bv.w;
    *(float4*)(out + (size_t)m * FDIM + c4) = o;
}

// ---------------- launch ----------------------------------------------------
extern "C" void kernel_launch(void* const* d_in, const int* in_sizes, int n_in,
                              void* d_out, int out_size) {
    const float* adj  = (const float*)d_in[0];
    const float* X    = (const float*)d_in[1];
    const float* W    = (const float*)d_in[2];
    const float* bias = (const float*)d_in[3];
    const void*  lptr = d_in[4];
    float* out = (float*)d_out;

    cudaFuncSetAttribute(k_gemm, cudaFuncAttributeMaxDynamicSharedMemorySize,
                         SMEM_BYTES);

    k_deg<<<N_NODES, 256>>>(adj, lptr);
    k_support<<<dim3(N_NODES / 64, FDIM / 64), 256>>>(X, W);
    k_gemm<<<(N_NODES / BM) * KSPL, 256, SMEM_BYTES>>>(adj);
    k_out<<<(N_NODES * FDIM / 4) / 256, 256>>>(bias, out);
}